// round 16
// baseline (speedup 1.0000x reference)
#include <cuda_runtime.h>
#include <cuda_fp16.h>
#include <math.h>
#include <cstdint>

#define BB 64
#define NN 128
#define XS 9   // words per edge row in s_x1 (stride padding)

// scratch for intermediate coors/vel between layers (no allocs allowed)
__device__ float g_c0[BB*NN*2];
__device__ float g_v0[BB*NN*2];
__device__ float g_c1[BB*NN*2];
__device__ float g_v1[BB*NN*2];

union F2U { float2 f; unsigned long long u; };
union H2U { __half2 h; uint32_t u; };

__device__ __forceinline__ float2 ffma2(float2 a, float2 b, float2 c) {
    F2U A, B, C, R;
    A.f = a; B.f = b; C.f = c;
    asm("fma.rn.f32x2 %0, %1, %2, %3;" : "=l"(R.u) : "l"(A.u), "l"(B.u), "l"(C.u));
    return R.f;
}

// ---- packed f16x2 silu machinery ----
__device__ __forceinline__ uint32_t f2_to_h2(float2 v) {
    uint32_t r;
    asm("cvt.rn.f16x2.f32 %0, %1, %2;" : "=r"(r) : "f"(v.y), "f"(v.x));
    return r;
}
__device__ __forceinline__ uint32_t tanh_h2(uint32_t x) {
    uint32_t r;
    asm("tanh.approx.f16x2 %0, %1;" : "=r"(r) : "r"(x));
    return r;
}
__device__ __forceinline__ uint32_t hfma2u(uint32_t a, uint32_t b, uint32_t c) {
    H2U A, B, C, R;
    A.u = a; B.u = b; C.u = c;
    R.h = __hfma2(A.h, B.h, C.h);
    return R.u;
}
__device__ __forceinline__ uint32_t hmul2u(uint32_t a, uint32_t b) {
    H2U A, B, R;
    A.u = a; B.u = b;
    R.h = __hmul2(A.h, B.h);
    return R.u;
}
__device__ __forceinline__ uint32_t silu_h2_pre(uint32_t h) {
    return hfma2u(h, tanh_h2(h), h);
}
__device__ __forceinline__ uint32_t silu_h2(uint32_t x) {
    H2U half_c; half_c.h = __floats2half2_rn(0.5f, 0.5f);
    return silu_h2_pre(hmul2u(x, half_c.u));
}

__device__ __forceinline__ float seluf(float x) {
    const float scale = 1.0507009873554805f;
    const float alpha = 1.6732632423543772f;
    return x > 0.0f ? scale * x : scale * alpha * expm1f(x);
}

__device__ __forceinline__ uint32_t pack_h2s(float a, float b) {
    H2U c; c.h = __floats2half2_rn(a, b);
    return c.u;
}
__device__ __forceinline__ float h16res(float v) {
    return v - __half2float(__float2half_rn(v));
}

// mma.m16n8k16, f32 C/D (final Wc2 dot only)
__device__ __forceinline__ void mma16816c(float& d0, float& d1, float& d2, float& d3,
                                          uint32_t a0, uint32_t a1, uint32_t a2, uint32_t a3,
                                          uint32_t b0, uint32_t b1,
                                          float c0, float c1, float c2, float c3) {
    asm("mma.sync.aligned.m16n8k16.row.col.f32.f16.f16.f32 "
        "{%0,%1,%2,%3}, {%4,%5,%6,%7}, {%8,%9}, {%10,%11,%12,%13};"
        : "=f"(d0), "=f"(d1), "=f"(d2), "=f"(d3)
        : "r"(a0), "r"(a1), "r"(a2), "r"(a3), "r"(b0), "r"(b1),
          "f"(c0), "f"(c1), "f"(c2), "f"(c3));
}

// mma.m16n8k16, f16 C/D
__device__ __forceinline__ void mma16816h(uint32_t& d0, uint32_t& d1,
                                          uint32_t a0, uint32_t a1, uint32_t a2, uint32_t a3,
                                          uint32_t b0, uint32_t b1,
                                          uint32_t c0, uint32_t c1) {
    asm("mma.sync.aligned.m16n8k16.row.col.f16.f16.f16.f16 "
        "{%0,%1}, {%2,%3,%4,%5}, {%6,%7}, {%8,%9};"
        : "=r"(d0), "=r"(d1)
        : "r"(a0), "r"(a1), "r"(a2), "r"(a3), "r"(b0), "r"(b1),
          "r"(c0), "r"(c1));
}

__global__ __launch_bounds__(128, 4)
void egnn_layer_kernel(const float* __restrict__ t,
                       const float* __restrict__ cin,
                       const float* __restrict__ vin,
                       float* __restrict__ cout,
                       float* __restrict__ vout,
                       const float* __restrict__ We1,
                       const float* __restrict__ be1,
                       const float* __restrict__ We2,
                       const float* __restrict__ be2,
                       const float* __restrict__ Wc1,
                       const float* __restrict__ bc1,
                       const float* __restrict__ Wc2,
                       const float* __restrict__ bc2,
                       const float* __restrict__ Wv,
                       const float* __restrict__ bv,
                       int l)
{
    __shared__ float4 sUVp[8];
    __shared__ float4 sWCp[8];
    __shared__ uint32_t sbe2h[8];
    __shared__ float  sWe2raw[256];
    __shared__ float  sWc1raw[1024];
    __shared__ uint32_t sbc1h[32];
    __shared__ float  sWc2s[64];
    __shared__ float2 scj2[NN];
    __shared__ float  stj[NN];
    __shared__ uint32_t s_x1[4 * NN * XS];
    __shared__ uint32_t s_fb2[4 * 32];
    __shared__ uint32_t s_fb3[16 * 32];
    __shared__ uint32_t s_fbd[8 * 32];

    const int tid   = threadIdx.x;
    const int wid   = tid >> 5;
    const int ln    = tid & 31;
    const int bb    = blockIdx.x >> 5;
    const int ibase = (blockIdx.x & 31) * 4;
    const int i     = ibase + wid;

    // ---- staging: raw weights ----
    const float* we1 = We1 + l * 128;
    if (tid < 8) {
        int c0 = 2 * tid, c1 = 2 * tid + 1;
        float u0 = 0.5f * (we1[c0] + we1[16 + c0] + we1[32 + c0]);
        float u1 = 0.5f * (we1[c1] + we1[16 + c1] + we1[32 + c1]);
        float v0 = 0.5f * (we1[48 + c0] + we1[64 + c0] + we1[80 + c0]);
        float v1 = 0.5f * (we1[48 + c1] + we1[64 + c1] + we1[80 + c1]);
        float w0 = 0.5f * we1[96 + c0];
        float w1 = 0.5f * we1[96 + c1];
        float k0 = 0.5f * (we1[112 + c0] + be1[l * 16 + c0]);
        float k1 = 0.5f * (we1[112 + c1] + be1[l * 16 + c1]);
        sUVp[tid] = make_float4(u0, u1, v0, v1);
        sWCp[tid] = make_float4(w0, w1, k0, k1);
        sbe2h[tid] = pack_h2s(0.5f * be2[l * 16 + c0], 0.5f * be2[l * 16 + c1]);
    } else if (tid < 40) {
        int k = tid - 8;
        sbc1h[k] = pack_h2s(0.5f * bc1[l * 64 + 2 * k], 0.5f * bc1[l * 64 + 2 * k + 1]);
    } else if (tid < 104) {
        sWc2s[tid - 40] = Wc2[l * 64 + tid - 40];
    }
    #pragma unroll
    for (int idx = tid; idx < 256; idx += 128)
        sWe2raw[idx] = 0.5f * We2[l * 256 + idx];
    #pragma unroll
    for (int idx = tid; idx < 1024; idx += 128)
        sWc1raw[idx] = 0.5f * Wc1[l * 1024 + idx];
    {
        const float2* c2 = (const float2*)(cin + bb * NN * 2);
        scj2[tid] = c2[tid];
        stj[tid]  = t[bb * NN + tid];
    }
    __syncthreads();

    const int p = ln & 3;
    const int g = ln >> 2;

    // ---- warp 0 prepacks per-lane B fragments into shared ----
    if (wid == 0) {
        #pragma unroll
        for (int nt = 0; nt < 2; ++nt) {
            int col = nt * 8 + g;
            s_fb2[(nt * 2 + 0) * 32 + ln] =
                pack_h2s(sWe2raw[(2 * p) * 16 + col],     sWe2raw[(2 * p + 1) * 16 + col]);
            s_fb2[(nt * 2 + 1) * 32 + ln] =
                pack_h2s(sWe2raw[(2 * p + 8) * 16 + col], sWe2raw[(2 * p + 9) * 16 + col]);
        }
        #pragma unroll
        for (int nt = 0; nt < 8; ++nt) {
            int col = nt * 8 + g;
            s_fb3[(nt * 2 + 0) * 32 + ln] =
                pack_h2s(sWc1raw[(2 * p) * 64 + col],     sWc1raw[(2 * p + 1) * 64 + col]);
            s_fb3[(nt * 2 + 1) * 32 + ln] =
                pack_h2s(sWc1raw[(2 * p + 8) * 64 + col], sWc1raw[(2 * p + 9) * 64 + col]);
        }
        #pragma unroll
        for (int c = 0; c < 4; ++c) {
            uint32_t lo = 0u, hi = 0u;
            if (g == 0) {
                lo = pack_h2s(sWc2s[16 * c + 2 * p],     sWc2s[16 * c + 2 * p + 1]);
                hi = pack_h2s(sWc2s[16 * c + 2 * p + 8], sWc2s[16 * c + 2 * p + 9]);
            } else if (g == 1) {
                lo = pack_h2s(h16res(sWc2s[16 * c + 2 * p]),
                              h16res(sWc2s[16 * c + 2 * p + 1]));
                hi = pack_h2s(h16res(sWc2s[16 * c + 2 * p + 8]),
                              h16res(sWc2s[16 * c + 2 * p + 9]));
            }
            s_fbd[(c * 2 + 0) * 32 + ln] = lo;
            s_fbd[(c * 2 + 1) * 32 + ln] = hi;
        }
    }

    const float ti  = stj[i];
    const float2 ci = scj2[i];
    const float2 ti2 = make_float2(ti, ti);
    const uint32_t be2h0 = sbe2h[p];
    const uint32_t be2h1 = sbe2h[p + 4];

    // ---- phase 1: x1 (f32 matvec, f16x2 silu) -> f16 edge-major shared ----
    uint32_t* sx = s_x1 + wid * NN * XS;
    #pragma unroll
    for (int ee = 0; ee < 4; ++ee) {
        const int e = ln + 32 * ee;
        const float tj = stj[e];
        const float2 cj = scj2[e];
        const float dx = ci.x - cj.x;
        const float dy = ci.y - cj.y;
        const float d = fmaf(dx, dx, dy * dy);
        const float2 tj2 = make_float2(tj, tj);
        const float2 d2  = make_float2(d, d);
        #pragma unroll
        for (int cp = 0; cp < 8; ++cp) {
            float4 uv = sUVp[cp];
            float4 wc = sWCp[cp];
            float2 h = ffma2(ti2, make_float2(uv.x, uv.y),
                      ffma2(tj2, make_float2(uv.z, uv.w),
                      ffma2(d2,  make_float2(wc.x, wc.y),
                                 make_float2(wc.z, wc.w))));
            sx[e * XS + cp] = silu_h2_pre(f2_to_h2(h));
        }
    }
    __syncthreads();

    const uint32_t b2f00 = s_fb2[0 * 32 + ln];
    const uint32_t b2f01 = s_fb2[1 * 32 + ln];
    const uint32_t b2f10 = s_fb2[2 * 32 + ln];
    const uint32_t b2f11 = s_fb2[3 * 32 + ln];

    // ---- phase 2: 2 iterations x 4 independent 16-edge tiles (4-way ILP) ----
    const float bc2c = (p == 0) ? bc2[l] : 0.0f;
    float ax = 0.0f, ay = 0.0f;

    #pragma unroll
    for (int rr = 0; rr < 2; ++rr) {
        // MLP2 for all 4 tiles
        uint32_t q[4][4];
        #pragma unroll
        for (int tt = 0; tt < 4; ++tt) {
            const int elo = 16 * (4 * rr + tt) + g;
            const int ehi = elo + 8;
            uint32_t a0 = sx[elo * XS + p];
            uint32_t a1 = sx[ehi * XS + p];
            uint32_t a2 = sx[elo * XS + p + 4];
            uint32_t a3 = sx[ehi * XS + p + 4];
            uint32_t D0, D1, D2, D3;
            mma16816h(D0, D1, a0, a1, a2, a3, b2f00, b2f01, be2h0, be2h0);
            mma16816h(D2, D3, a0, a1, a2, a3, b2f10, b2f11, be2h1, be2h1);
            q[tt][0] = silu_h2(silu_h2_pre(D0));
            q[tt][1] = silu_h2(silu_h2_pre(D1));
            q[tt][2] = silu_h2(silu_h2_pre(D2));
            q[tt][3] = silu_h2(silu_h2_pre(D3));
        }

        // MLP3 + dot, 4 tiles per K-chunk
        float w[4][4];
        #pragma unroll
        for (int tt = 0; tt < 4; ++tt) {
            w[tt][0] = bc2c; w[tt][1] = 0.0f; w[tt][2] = bc2c; w[tt][3] = 0.0f;
        }
        #pragma unroll
        for (int c = 0; c < 4; ++c) {
            uint32_t bfa0 = s_fb3[(4 * c + 0) * 32 + ln];
            uint32_t bfa1 = s_fb3[(4 * c + 1) * 32 + ln];
            uint32_t bfb0 = s_fb3[(4 * c + 2) * 32 + ln];
            uint32_t bfb1 = s_fb3[(4 * c + 3) * 32 + ln];
            uint32_t bdl  = s_fbd[(2 * c + 0) * 32 + ln];
            uint32_t bdh  = s_fbd[(2 * c + 1) * 32 + ln];
            uint32_t bb0 = sbc1h[4 * (2 * c) + p];
            uint32_t bb1 = sbc1h[4 * (2 * c + 1) + p];
            #pragma unroll
            for (int tt = 0; tt < 4; ++tt) {
                uint32_t D0, D1, E0, E1;
                mma16816h(D0, D1, q[tt][0], q[tt][1], q[tt][2], q[tt][3],
                          bfa0, bfa1, bb0, bb0);
                mma16816h(E0, E1, q[tt][0], q[tt][1], q[tt][2], q[tt][3],
                          bfb0, bfb1, bb1, bb1);
                uint32_t h0 = silu_h2_pre(D0);
                uint32_t h1 = silu_h2_pre(D1);
                uint32_t h2 = silu_h2_pre(E0);
                uint32_t h3 = silu_h2_pre(E1);
                mma16816c(w[tt][0], w[tt][1], w[tt][2], w[tt][3],
                          h0, h1, h2, h3, bdl, bdh,
                          w[tt][0], w[tt][1], w[tt][2], w[tt][3]);
            }
        }

        // epilogue per tile
        #pragma unroll
        for (int tt = 0; tt < 4; ++tt) {
            const int elo = 16 * (4 * rr + tt) + g;
            const int ehi = elo + 8;
            float wE  = w[tt][0] + w[tt][1];
            float wE8 = w[tt][2] + w[tt][3];
            float2 cjE  = scj2[elo];
            float2 cjE8 = scj2[ehi];
            ax += wE * (ci.x - cjE.x) + wE8 * (ci.x - cjE8.x);
            ay += wE * (ci.y - cjE.y) + wE8 * (ci.y - cjE8.y);
        }
    }

    // ---- warp reduce + node update ----
    #pragma unroll
    for (int off = 16; off > 0; off >>= 1) {
        ax += __shfl_down_sync(0xFFFFFFFFu, ax, off);
        ay += __shfl_down_sync(0xFFFFFFFFu, ay, off);
    }
    if (ln == 0) {
        float wv  = Wv[l * 3] + Wv[l * 3 + 1] + Wv[l * 3 + 2];
        float phi = fmaf(ti, wv, bv[l]);
        float vx = vin[(bb * NN + i) * 2];
        float vy = vin[(bb * NN + i) * 2 + 1];
        float nvx = fmaf(phi, vx, ax);
        float nvy = fmaf(phi, vy, ay);
        float ncx = ci.x + nvx;
        float ncy = ci.y + nvy;
        cout[(bb * NN + i) * 2]     = seluf(ncx);
        cout[(bb * NN + i) * 2 + 1] = seluf(ncy);
        vout[(bb * NN + i) * 2]     = seluf(nvx);
        vout[(bb * NN + i) * 2 + 1] = seluf(nvy);
    }
}

__global__ void egnn_head_kernel(const float* __restrict__ cin,
                                 const float* __restrict__ vin,
                                 const float* __restrict__ Wconv1,
                                 const float* __restrict__ bconv1,
                                 const float* __restrict__ Wconv2,
                                 const float* __restrict__ bconv2,
                                 float* __restrict__ out)
{
    int idx = blockIdx.x * blockDim.x + threadIdx.x;
    if (idx >= BB * NN) return;

    float x0 = seluf(cin[idx * 2]);
    float x1 = seluf(cin[idx * 2 + 1]);
    float x2 = seluf(vin[idx * 2]);
    float x3 = seluf(vin[idx * 2 + 1]);

    float y0 = bconv2[0], y1 = bconv2[1], y2 = bconv2[2], y3 = bconv2[3];
    #pragma unroll
    for (int o = 0; o < 32; o++) {
        float h = bconv1[o];
        h = fmaf(x0, Wconv1[o * 4 + 0], h);
        h = fmaf(x1, Wconv1[o * 4 + 1], h);
        h = fmaf(x2, Wconv1[o * 4 + 2], h);
        h = fmaf(x3, Wconv1[o * 4 + 3], h);
        h = seluf(h);
        y0 = fmaf(h, Wconv2[0 * 32 + o], y0);
        y1 = fmaf(h, Wconv2[1 * 32 + o], y1);
        y2 = fmaf(h, Wconv2[2 * 32 + o], y2);
        y3 = fmaf(h, Wconv2[3 * 32 + o], y3);
    }
    out[idx * 2]                   = y0;
    out[idx * 2 + 1]               = y1;
    out[BB * NN * 2 + idx * 2]     = y2;
    out[BB * NN * 2 + idx * 2 + 1] = y3;
}

extern "C" void kernel_launch(void* const* d_in, const int* in_sizes, int n_in,
                              void* d_out, int out_size)
{
    const float* t      = (const float*)d_in[0];
    const float* coors  = (const float*)d_in[1];
    const float* vel    = (const float*)d_in[2];
    const float* We1    = (const float*)d_in[3];
    const float* be1    = (const float*)d_in[4];
    const float* We2    = (const float*)d_in[5];
    const float* be2    = (const float*)d_in[6];
    const float* Wc1    = (const float*)d_in[7];
    const float* bc1    = (const float*)d_in[8];
    const float* Wc2    = (const float*)d_in[9];
    const float* bc2    = (const float*)d_in[10];
    const float* Wv     = (const float*)d_in[11];
    const float* bv     = (const float*)d_in[12];
    const float* Wconv1 = (const float*)d_in[13];
    const float* bconv1 = (const float*)d_in[14];
    const float* Wconv2 = (const float*)d_in[15];
    const float* bconv2 = (const float*)d_in[16];
    float* out = (float*)d_out;

    float *c0, *v0, *c1, *v1;
    cudaGetSymbolAddress((void**)&c0, g_c0);
    cudaGetSymbolAddress((void**)&v0, g_v0);
    cudaGetSymbolAddress((void**)&c1, g_c1);
    cudaGetSymbolAddress((void**)&v1, g_v1);

    dim3 grid(BB * 32);   // 2048 blocks: (batch, group of 4 i's), warp-per-i
    dim3 blk(128);
    egnn_layer_kernel<<<grid, blk>>>(t, coors, vel, c0, v0,
                                     We1, be1, We2, be2, Wc1, bc1, Wc2, bc2,
                                     Wv, bv, 0);
    egnn_layer_kernel<<<grid, blk>>>(t, c0, v0, c1, v1,
                                     We1, be1, We2, be2, Wc1, bc1, Wc2, bc2,
                                     Wv, bv, 1);
    egnn_head_kernel<<<(BB * NN + 127) / 128, 128>>>(c1, v1, Wconv1, bconv1,
                                                     Wconv2, bconv2, out);
}